// round 1
// baseline (speedup 1.0000x reference)
#include <cuda_runtime.h>

// Problem constants (fixed shapes for this problem instance)
#define Dz 64
#define Hy 128
#define Wx 128
#define NPTS (Dz * Hy * Wx)          // 1,048,576
#define TBITS 21
#define TSIZE (1 << TBITS)           // 2,097,152 slots
#define TMASK (TSIZE - 1)
#define EMPTYK (-1)

// Scratch (device globals: no allocation allowed)
__device__ int      d_keys[TSIZE];
__device__ float    d_latA[TSIZE * 5];
__device__ float    d_latB[TSIZE * 5];
__device__ unsigned d_slots[4 * NPTS];

__device__ __forceinline__ unsigned tab_start(int h) {
    return ((unsigned)h * 2654435761u) >> (32 - TBITS);
}

__device__ __forceinline__ int tab_insert(int h) {
    unsigned idx = tab_start(h);
    for (;;) {
        int prev = atomicCAS(&d_keys[idx], EMPTYK, h);
        if (prev == EMPTYK || prev == h) return (int)idx;
        idx = (idx + 1) & TMASK;
    }
}

__device__ __forceinline__ int tab_find(int h) {
    unsigned idx = tab_start(h);
    for (;;) {
        int k = d_keys[idx];
        if (k == h) return (int)idx;
        if (k == EMPTYK) return -1;
        idx = (idx + 1) & TMASK;
    }
}

// Permutohedral lattice geometry for one point: 4 packed keys + 4 barycentric weights.
// Exactly mirrors the reference math (float32 throughout).
__device__ __forceinline__ void lattice(float f0, float f1, float f2,
                                        int* hh, float* bary) {
    // E matrix columns pre-scaled: inv_std/sqrt(j(j+1))
    const float s0 = 2.3094010767585034f;   // sqrt(2/3)*4 / sqrt(2)
    const float s1 = 1.3333333333333333f;   // / sqrt(6)
    const float s2 = 0.9428090415820634f;   // / sqrt(12)
    float c0 = f0 * s0, c1 = f1 * s1, c2 = f2 * s2;
    float el[4];
    el[0] =  c0 + c1 + c2;
    el[1] = -c0 + c1 + c2;
    el[2] = -2.f * c1 + c2;
    el[3] = -3.f * c2;

    float rem0[4];
    float sum = 0.f;
#pragma unroll
    for (int i = 0; i < 4; i++) {
        float v  = el[i] * 0.25f;
        float up = ceilf(v), dn = floorf(v);
        float r  = (((up - v) < (v - dn)) ? up : dn) * 4.f;
        rem0[i] = r;
        sum += r;
    }

    float diff[4];
    int rank[4] = {0, 0, 0, 0};
#pragma unroll
    for (int i = 0; i < 4; i++) diff[i] = el[i] - rem0[i];
#pragma unroll
    for (int i = 0; i < 4; i++) {
#pragma unroll
        for (int j = i + 1; j < 4; j++) {
            if (diff[i] < diff[j]) rank[i]++; else rank[j]++;
        }
    }

    int off = (int)rintf(sum * 0.25f);
#pragma unroll
    for (int i = 0; i < 4; i++) {
        rank[i] += off;
        if (rank[i] < 0)      { rank[i] += 4; rem0[i] += 4.f; }
        else if (rank[i] > 3) { rank[i] -= 4; rem0[i] -= 4.f; }
    }

    float b[5] = {0.f, 0.f, 0.f, 0.f, 0.f};
#pragma unroll
    for (int i = 0; i < 4; i++) {
        float t = (el[i] - rem0[i]) * 0.25f;
        b[3 - rank[i]] += t;
        b[4 - rank[i]] -= t;
    }
    b[0] += 1.f + b[4];

    int r0 = (int)rem0[0], r1 = (int)rem0[1], r2 = (int)rem0[2];
#pragma unroll
    for (int r = 0; r < 4; r++) {
        int k0 = r0 + ((rank[0] >= 4 - r) ? r - 4 : r);
        int k1 = r1 + ((rank[1] >= 4 - r) ? r - 4 : r);
        int k2 = r2 + ((rank[2] >= 4 - r) ? r - 4 : r);
        hh[r]  = ((k0 + 512) << 20) + ((k1 + 512) << 10) + (k2 + 512);
        bary[r] = b[r];
    }
}

__device__ __forceinline__ void point_features(int n, const float* vg, const float* sg,
                                               float& f0, float& f1, float& f2) {
    int x = n & (Wx - 1);
    int y = (n >> 7) & (Hy - 1);
    int z = n >> 14;
    // feature order in reference: [zz, yy, xx] with yy using index 2, xx index 1
    f0 = vg[0] * (float)z / sg[0];
    f1 = vg[2] * (float)y / sg[2];
    f2 = vg[1] * (float)x / sg[1];
}

__global__ void k_reset() {
    int i = blockIdx.x * blockDim.x + threadIdx.x;
    if (i < TSIZE) d_keys[i] = EMPTYK;
    if (i < TSIZE * 5) d_latA[i] = 0.f;
}

__global__ void k_splat(const float* __restrict__ vals,
                        const float* __restrict__ vg,
                        const float* __restrict__ sg) {
    int n = blockIdx.x * blockDim.x + threadIdx.x;
    if (n >= NPTS) return;
    float f0, f1, f2;
    point_features(n, vg, sg, f0, f1, f2);

    int hh[4]; float bary[4];
    lattice(f0, f1, f2, hh, bary);

    float v0 = vals[n];
    float v1 = vals[NPTS + n];
    float v2 = vals[2 * NPTS + n];
    float v3 = vals[3 * NPTS + n];

    int lane = threadIdx.x & 31;

#pragma unroll
    for (int r = 0; r < 4; r++) {
        int   h = hh[r];
        float w = bary[r];
        float a0 = w * v0, a1 = w * v1, a2 = w * v2, a3 = w * v3, a4 = w;

        // Warp aggregation: neighboring pixels share lattice vertices.
        unsigned mask   = __match_any_sync(0xffffffffu, h);
        int      leader = __ffs(mask) - 1;

        float s0 = 0.f, s1 = 0.f, s2 = 0.f, s3 = 0.f, s4 = 0.f;
        for (unsigned m = mask; m; m &= m - 1) {
            int src = __ffs(m) - 1;
            s0 += __shfl_sync(mask, a0, src);
            s1 += __shfl_sync(mask, a1, src);
            s2 += __shfl_sync(mask, a2, src);
            s3 += __shfl_sync(mask, a3, src);
            s4 += __shfl_sync(mask, a4, src);
        }

        int slot = 0;
        if (lane == leader) {
            slot = tab_insert(h);
            float* p = &d_latA[slot * 5];
            atomicAdd(p + 0, s0);
            atomicAdd(p + 1, s1);
            atomicAdd(p + 2, s2);
            atomicAdd(p + 3, s3);
            atomicAdd(p + 4, s4);
        }
        slot = __shfl_sync(mask, slot, leader);
        d_slots[r * NPTS + n] = (unsigned)slot;
    }
}

__global__ void k_blur(int dh, int srcIsA) {
    int s = blockIdx.x * blockDim.x + threadIdx.x;
    if (s >= TSIZE) return;
    int h = d_keys[s];
    if (h == EMPTYK) return;

    const float* src = srcIsA ? d_latA : d_latB;
    float*       dst = srcIsA ? d_latB : d_latA;

    int p = tab_find(h + dh);
    int q = tab_find(h - dh);
#pragma unroll
    for (int j = 0; j < 5; j++) {
        float a = (p >= 0) ? src[p * 5 + j] : 0.f;
        float b = (q >= 0) ? src[q * 5 + j] : 0.f;
        dst[s * 5 + j] = src[s * 5 + j] + 0.5f * (a + b);
    }
}

__global__ void k_slice(const float* __restrict__ vg,
                        const float* __restrict__ sg,
                        float* __restrict__ out) {
    int n = blockIdx.x * blockDim.x + threadIdx.x;
    if (n >= NPTS) return;
    float f0, f1, f2;
    point_features(n, vg, sg, f0, f1, f2);

    int hh[4]; float bary[4];
    lattice(f0, f1, f2, hh, bary);

    float acc0 = 0.f, acc1 = 0.f, acc2 = 0.f, acc3 = 0.f, acc4 = 0.f;
#pragma unroll
    for (int r = 0; r < 4; r++) {
        unsigned s = d_slots[r * NPTS + n];
        float    w = bary[r];
        const float* p = &d_latA[s * 5];
        acc0 += w * p[0];
        acc1 += w * p[1];
        acc2 += w * p[2];
        acc3 += w * p[3];
        acc4 += w * p[4];
    }
    const float alpha = 1.f / 1.125f;  // 1/(1 + 2^-PD)
    float norm = alpha * acc4 + 2.220446049250313e-16f;
    float inv  = 1.f / norm;
    out[0 * NPTS + n] = alpha * acc0 * inv;
    out[1 * NPTS + n] = alpha * acc1 * inv;
    out[2 * NPTS + n] = alpha * acc2 * inv;
    out[3 * NPTS + n] = alpha * acc3 * inv;
}

extern "C" void kernel_launch(void* const* d_in, const int* in_sizes, int n_in,
                              void* d_out, int out_size) {
    const float* input = nullptr;
    const float* vg = nullptr;
    const float* sg = nullptr;
    for (int i = 0; i < n_in; i++) {
        if (in_sizes[i] == 4 * NPTS) input = (const float*)d_in[i];
        else if (in_sizes[i] == 3) {
            if (!vg) vg = (const float*)d_in[i];
            else     sg = (const float*)d_in[i];
        }
    }
    float* out = (float*)d_out;

    // Neighbor hash deltas for the 4 blur directions (packing is linear in key comps)
    const int DH0 = -3 * (1 << 20) + (1 << 10) + 1;  // o = (-3, 1, 1)
    const int DH1 =      (1 << 20) - 3 * (1 << 10) + 1;  // o = (1, -3, 1)
    const int DH2 =      (1 << 20) + (1 << 10) - 3;  // o = (1, 1, -3)
    const int DH3 =      (1 << 20) + (1 << 10) + 1;  // o = (1, 1, 1)

    k_reset<<<(TSIZE * 5 + 255) / 256, 256>>>();
    k_splat<<<NPTS / 256, 256>>>(input, vg, sg);
    k_blur<<<TSIZE / 256, 256>>>(DH0, 1);  // A -> B
    k_blur<<<TSIZE / 256, 256>>>(DH1, 0);  // B -> A
    k_blur<<<TSIZE / 256, 256>>>(DH2, 1);  // A -> B
    k_blur<<<TSIZE / 256, 256>>>(DH3, 0);  // B -> A (final in A)
    k_slice<<<NPTS / 256, 256>>>(vg, sg, out);
}

// round 2
// speedup vs baseline: 1.2648x; 1.2648x over previous
#include <cuda_runtime.h>

// Problem constants (fixed shapes for this problem instance)
#define Dz 64
#define Hy 128
#define Wx 128
#define NPTS (Dz * Hy * Wx)          // 1,048,576
#define TBITS 21
#define TSIZE (1 << TBITS)           // 2,097,152 slots
#define TMASK (TSIZE - 1)
#define EMPTYK 0                     // packed hash is never 0; zero-init == empty
#define LISTCAP (1 << 20)

// Scratch (device globals: no allocation allowed; zero-initialized at load)
__device__ int      d_keys[TSIZE];
__device__ float    d_latA[TSIZE * 5];
__device__ float    d_latB[TSIZE * 5];
__device__ unsigned d_slots[4 * NPTS];
__device__ int      d_list[LISTCAP];
__device__ int      d_count;

__device__ __forceinline__ unsigned tab_start(int h) {
    return ((unsigned)h * 2654435761u) >> (32 - TBITS);
}

__device__ __forceinline__ int tab_insert(int h) {
    unsigned idx = tab_start(h);
    for (;;) {
        int prev = atomicCAS(&d_keys[idx], EMPTYK, h);
        if (prev == EMPTYK) {
            int i = atomicAdd(&d_count, 1);
            d_list[i] = (int)idx;
            return (int)idx;
        }
        if (prev == h) return (int)idx;
        idx = (idx + 1) & TMASK;
    }
}

__device__ __forceinline__ int tab_find(int h) {
    unsigned idx = tab_start(h);
    for (;;) {
        int k = d_keys[idx];
        if (k == h) return (int)idx;
        if (k == EMPTYK) return -1;
        idx = (idx + 1) & TMASK;
    }
}

// Permutohedral lattice geometry for one point: 4 packed keys + 4 barycentric weights.
// Exactly mirrors the reference math (float32 throughout).
__device__ __forceinline__ void lattice(float f0, float f1, float f2,
                                        int* hh, float* bary) {
    const float s0 = 2.3094010767585034f;   // sqrt(2/3)*4 / sqrt(2)
    const float s1 = 1.3333333333333333f;   // / sqrt(6)
    const float s2 = 0.9428090415820634f;   // / sqrt(12)
    float c0 = f0 * s0, c1 = f1 * s1, c2 = f2 * s2;
    float el[4];
    el[0] =  c0 + c1 + c2;
    el[1] = -c0 + c1 + c2;
    el[2] = -2.f * c1 + c2;
    el[3] = -3.f * c2;

    float rem0[4];
    float sum = 0.f;
#pragma unroll
    for (int i = 0; i < 4; i++) {
        float v  = el[i] * 0.25f;
        float up = ceilf(v), dn = floorf(v);
        float r  = (((up - v) < (v - dn)) ? up : dn) * 4.f;
        rem0[i] = r;
        sum += r;
    }

    float diff[4];
    int rank[4] = {0, 0, 0, 0};
#pragma unroll
    for (int i = 0; i < 4; i++) diff[i] = el[i] - rem0[i];
#pragma unroll
    for (int i = 0; i < 4; i++) {
#pragma unroll
        for (int j = i + 1; j < 4; j++) {
            if (diff[i] < diff[j]) rank[i]++; else rank[j]++;
        }
    }

    int off = (int)rintf(sum * 0.25f);
#pragma unroll
    for (int i = 0; i < 4; i++) {
        rank[i] += off;
        if (rank[i] < 0)      { rank[i] += 4; rem0[i] += 4.f; }
        else if (rank[i] > 3) { rank[i] -= 4; rem0[i] -= 4.f; }
    }

    float b[5] = {0.f, 0.f, 0.f, 0.f, 0.f};
#pragma unroll
    for (int i = 0; i < 4; i++) {
        float t = (el[i] - rem0[i]) * 0.25f;
        b[3 - rank[i]] += t;
        b[4 - rank[i]] -= t;
    }
    b[0] += 1.f + b[4];

    int r0 = (int)rem0[0], r1 = (int)rem0[1], r2 = (int)rem0[2];
#pragma unroll
    for (int r = 0; r < 4; r++) {
        int k0 = r0 + ((rank[0] >= 4 - r) ? r - 4 : r);
        int k1 = r1 + ((rank[1] >= 4 - r) ? r - 4 : r);
        int k2 = r2 + ((rank[2] >= 4 - r) ? r - 4 : r);
        hh[r]  = ((k0 + 512) << 20) + ((k1 + 512) << 10) + (k2 + 512);
        bary[r] = b[r];
    }
}

__device__ __forceinline__ void point_features(int n, const float* vg, const float* sg,
                                               float& f0, float& f1, float& f2) {
    int x = n & (Wx - 1);
    int y = (n >> 7) & (Hy - 1);
    int z = n >> 14;
    // feature order in reference: [zz, yy, xx] with yy using index 2, xx index 1
    f0 = vg[0] * (float)z / sg[0];
    f1 = vg[2] * (float)y / sg[2];
    f2 = vg[1] * (float)x / sg[1];
}

__global__ void k_rstcnt() { d_count = 0; }

__global__ void k_splat(const float* __restrict__ vals,
                        const float* __restrict__ vg,
                        const float* __restrict__ sg) {
    int n = blockIdx.x * blockDim.x + threadIdx.x;
    if (n >= NPTS) return;
    float f0, f1, f2;
    point_features(n, vg, sg, f0, f1, f2);

    int hh[4]; float bary[4];
    lattice(f0, f1, f2, hh, bary);

    float v0 = vals[n];
    float v1 = vals[NPTS + n];
    float v2 = vals[2 * NPTS + n];
    float v3 = vals[3 * NPTS + n];

    int lane = threadIdx.x & 31;

#pragma unroll
    for (int r = 0; r < 4; r++) {
        int   h = hh[r];
        float w = bary[r];
        float a0 = w * v0, a1 = w * v1, a2 = w * v2, a3 = w * v3, a4 = w;

        // Warp aggregation: neighboring pixels share lattice vertices.
        unsigned mask   = __match_any_sync(0xffffffffu, h);
        int      leader = __ffs(mask) - 1;

        float s0 = 0.f, s1 = 0.f, s2 = 0.f, s3 = 0.f, s4 = 0.f;
        for (unsigned m = mask; m; m &= m - 1) {
            int src = __ffs(m) - 1;
            s0 += __shfl_sync(mask, a0, src);
            s1 += __shfl_sync(mask, a1, src);
            s2 += __shfl_sync(mask, a2, src);
            s3 += __shfl_sync(mask, a3, src);
            s4 += __shfl_sync(mask, a4, src);
        }

        int slot = 0;
        if (lane == leader) {
            slot = tab_insert(h);
            float* p = &d_latA[slot * 5];
            atomicAdd(p + 0, s0);
            atomicAdd(p + 1, s1);
            atomicAdd(p + 2, s2);
            atomicAdd(p + 3, s3);
            atomicAdd(p + 4, s4);
        }
        slot = __shfl_sync(mask, slot, leader);
        d_slots[r * NPTS + n] = (unsigned)slot;
    }
}

// Blur over the compact occupied list only (~50k entries instead of 2M slots)
__global__ void k_blur(int dh, int srcIsA) {
    int total  = d_count;
    int stride = gridDim.x * blockDim.x;
    const float* src = srcIsA ? d_latA : d_latB;
    float*       dst = srcIsA ? d_latB : d_latA;

    for (int i = blockIdx.x * blockDim.x + threadIdx.x; i < total; i += stride) {
        int s = d_list[i];
        int h = d_keys[s];

        int p = tab_find(h + dh);
        int q = tab_find(h - dh);
#pragma unroll
        for (int j = 0; j < 5; j++) {
            float a = (p >= 0) ? src[p * 5 + j] : 0.f;
            float b = (q >= 0) ? src[q * 5 + j] : 0.f;
            dst[s * 5 + j] = src[s * 5 + j] + 0.5f * (a + b);
        }
    }
}

__global__ void k_slice(const float* __restrict__ vg,
                        const float* __restrict__ sg,
                        float* __restrict__ out) {
    int n = blockIdx.x * blockDim.x + threadIdx.x;
    if (n >= NPTS) return;
    float f0, f1, f2;
    point_features(n, vg, sg, f0, f1, f2);

    int hh[4]; float bary[4];
    lattice(f0, f1, f2, hh, bary);

    float acc0 = 0.f, acc1 = 0.f, acc2 = 0.f, acc3 = 0.f, acc4 = 0.f;
#pragma unroll
    for (int r = 0; r < 4; r++) {
        unsigned s = d_slots[r * NPTS + n];
        float    w = bary[r];
        const float* p = &d_latA[s * 5];
        acc0 += w * p[0];
        acc1 += w * p[1];
        acc2 += w * p[2];
        acc3 += w * p[3];
        acc4 += w * p[4];
    }
    const float alpha = 1.f / 1.125f;  // 1/(1 + 2^-PD)
    float norm = alpha * acc4 + 2.220446049250313e-16f;
    float inv  = 1.f / norm;
    out[0 * NPTS + n] = alpha * acc0 * inv;
    out[1 * NPTS + n] = alpha * acc1 * inv;
    out[2 * NPTS + n] = alpha * acc2 * inv;
    out[3 * NPTS + n] = alpha * acc3 * inv;
}

// Clear only the table entries we dirtied, so the next call starts clean
// without a 48MB full reset. latB needs no clearing: its occupied entries are
// fully overwritten by the first blur, and unoccupied entries are unreachable.
__global__ void k_cleanup() {
    int total  = d_count;
    int stride = gridDim.x * blockDim.x;
    for (int i = blockIdx.x * blockDim.x + threadIdx.x; i < total; i += stride) {
        int s = d_list[i];
        d_keys[s] = EMPTYK;
#pragma unroll
        for (int j = 0; j < 5; j++) d_latA[s * 5 + j] = 0.f;
    }
}

extern "C" void kernel_launch(void* const* d_in, const int* in_sizes, int n_in,
                              void* d_out, int out_size) {
    const float* input = nullptr;
    const float* vg = nullptr;
    const float* sg = nullptr;
    for (int i = 0; i < n_in; i++) {
        if (in_sizes[i] == 4 * NPTS) input = (const float*)d_in[i];
        else if (in_sizes[i] == 3) {
            if (!vg) vg = (const float*)d_in[i];
            else     sg = (const float*)d_in[i];
        }
    }
    float* out = (float*)d_out;

    // Neighbor hash deltas for the 4 blur directions (packing is linear in key comps)
    const int DH0 = -3 * (1 << 20) + (1 << 10) + 1;      // o = (-3, 1, 1)
    const int DH1 =      (1 << 20) - 3 * (1 << 10) + 1;  // o = (1, -3, 1)
    const int DH2 =      (1 << 20) + (1 << 10) - 3;      // o = (1, 1, -3)
    const int DH3 =      (1 << 20) + (1 << 10) + 1;      // o = (1, 1, 1)

    k_rstcnt<<<1, 1>>>();
    k_splat<<<NPTS / 256, 256>>>(input, vg, sg);
    k_blur<<<128, 256>>>(DH0, 1);  // A -> B
    k_blur<<<128, 256>>>(DH1, 0);  // B -> A
    k_blur<<<128, 256>>>(DH2, 1);  // A -> B
    k_blur<<<128, 256>>>(DH3, 0);  // B -> A (final in A)
    k_slice<<<NPTS / 256, 256>>>(vg, sg, out);
    k_cleanup<<<128, 256>>>();
}

// round 3
// speedup vs baseline: 1.3183x; 1.0423x over previous
#include <cuda_runtime.h>

// Problem constants (fixed shapes for this problem instance)
#define Dz 64
#define Hy 128
#define Wx 128
#define NPTS (Dz * Hy * Wx)          // 1,048,576
#define TBITS 21
#define TSIZE (1 << TBITS)           // 2,097,152 slots
#define TMASK (TSIZE - 1)
#define EMPTYK 0                     // packed hash is never 0; zero-init == empty
#define LISTCAP (1 << 20)
#define LSTRIDE 8                    // padded lattice row (floats): float4-friendly

// Scratch (device globals: no allocation allowed; zero-initialized at load)
// Row TSIZE is a sentinel that stays all-zero in both buffers.
__device__ int      d_keys[TSIZE];
__device__ float    d_latA[(TSIZE + 1) * LSTRIDE];
__device__ float    d_latB[(TSIZE + 1) * LSTRIDE];
__device__ unsigned d_slots[4 * NPTS];
__device__ int2     d_list[LISTCAP];     // (slot, hash)
__device__ int      d_nbr[8 * LISTCAP];  // dir-major neighbor slot indices
__device__ int      d_count;

__device__ __forceinline__ unsigned tab_start(int h) {
    return ((unsigned)h * 2654435761u) >> (32 - TBITS);
}

__device__ __forceinline__ int tab_insert(int h) {
    unsigned idx = tab_start(h);
    for (;;) {
        int prev = atomicCAS(&d_keys[idx], EMPTYK, h);
        if (prev == EMPTYK) {
            int i = atomicAdd(&d_count, 1);
            d_list[i] = make_int2((int)idx, h);
            return (int)idx;
        }
        if (prev == h) return (int)idx;
        idx = (idx + 1) & TMASK;
    }
}

// Returns slot, or TSIZE (sentinel zero row) if absent.
__device__ __forceinline__ int tab_find(int h) {
    unsigned idx = tab_start(h);
    for (;;) {
        int k = d_keys[idx];
        if (k == h) return (int)idx;
        if (k == EMPTYK) return TSIZE;
        idx = (idx + 1) & TMASK;
    }
}

// Permutohedral lattice geometry for one point: 4 packed keys + 4 barycentric weights.
__device__ __forceinline__ void lattice(float f0, float f1, float f2,
                                        int* hh, float* bary) {
    const float s0 = 2.3094010767585034f;
    const float s1 = 1.3333333333333333f;
    const float s2 = 0.9428090415820634f;
    float c0 = f0 * s0, c1 = f1 * s1, c2 = f2 * s2;
    float el[4];
    el[0] =  c0 + c1 + c2;
    el[1] = -c0 + c1 + c2;
    el[2] = -2.f * c1 + c2;
    el[3] = -3.f * c2;

    float rem0[4];
    float sum = 0.f;
#pragma unroll
    for (int i = 0; i < 4; i++) {
        float v  = el[i] * 0.25f;
        float up = ceilf(v), dn = floorf(v);
        float r  = (((up - v) < (v - dn)) ? up : dn) * 4.f;
        rem0[i] = r;
        sum += r;
    }

    float diff[4];
    int rank[4] = {0, 0, 0, 0};
#pragma unroll
    for (int i = 0; i < 4; i++) diff[i] = el[i] - rem0[i];
#pragma unroll
    for (int i = 0; i < 4; i++) {
#pragma unroll
        for (int j = i + 1; j < 4; j++) {
            if (diff[i] < diff[j]) rank[i]++; else rank[j]++;
        }
    }

    int off = (int)rintf(sum * 0.25f);
#pragma unroll
    for (int i = 0; i < 4; i++) {
        rank[i] += off;
        if (rank[i] < 0)      { rank[i] += 4; rem0[i] += 4.f; }
        else if (rank[i] > 3) { rank[i] -= 4; rem0[i] -= 4.f; }
    }

    float b[5] = {0.f, 0.f, 0.f, 0.f, 0.f};
#pragma unroll
    for (int i = 0; i < 4; i++) {
        float t = (el[i] - rem0[i]) * 0.25f;
        b[3 - rank[i]] += t;
        b[4 - rank[i]] -= t;
    }
    b[0] += 1.f + b[4];

    int r0 = (int)rem0[0], r1 = (int)rem0[1], r2 = (int)rem0[2];
#pragma unroll
    for (int r = 0; r < 4; r++) {
        int k0 = r0 + ((rank[0] >= 4 - r) ? r - 4 : r);
        int k1 = r1 + ((rank[1] >= 4 - r) ? r - 4 : r);
        int k2 = r2 + ((rank[2] >= 4 - r) ? r - 4 : r);
        hh[r]  = ((k0 + 512) << 20) + ((k1 + 512) << 10) + (k2 + 512);
        bary[r] = b[r];
    }
}

__device__ __forceinline__ void point_features(int n, const float* vg, const float* sg,
                                               float& f0, float& f1, float& f2) {
    int x = n & (Wx - 1);
    int y = (n >> 7) & (Hy - 1);
    int z = n >> 14;
    f0 = vg[0] * (float)z / sg[0];
    f1 = vg[2] * (float)y / sg[2];
    f2 = vg[1] * (float)x / sg[1];
}

__global__ void k_rstcnt() { d_count = 0; }

__global__ void k_splat(const float* __restrict__ vals,
                        const float* __restrict__ vg,
                        const float* __restrict__ sg) {
    int n = blockIdx.x * blockDim.x + threadIdx.x;
    if (n >= NPTS) return;
    float f0, f1, f2;
    point_features(n, vg, sg, f0, f1, f2);

    int hh[4]; float bary[4];
    lattice(f0, f1, f2, hh, bary);

    float v0 = vals[n];
    float v1 = vals[NPTS + n];
    float v2 = vals[2 * NPTS + n];
    float v3 = vals[3 * NPTS + n];

    int lane = threadIdx.x & 31;

#pragma unroll
    for (int r = 0; r < 4; r++) {
        int   h = hh[r];
        float w = bary[r];
        float a0 = w * v0, a1 = w * v1, a2 = w * v2, a3 = w * v3, a4 = w;

        unsigned mask   = __match_any_sync(0xffffffffu, h);
        int      leader = __ffs(mask) - 1;

        float s0 = 0.f, s1 = 0.f, s2 = 0.f, s3 = 0.f, s4 = 0.f;
        for (unsigned m = mask; m; m &= m - 1) {
            int src = __ffs(m) - 1;
            s0 += __shfl_sync(mask, a0, src);
            s1 += __shfl_sync(mask, a1, src);
            s2 += __shfl_sync(mask, a2, src);
            s3 += __shfl_sync(mask, a3, src);
            s4 += __shfl_sync(mask, a4, src);
        }

        int slot = 0;
        if (lane == leader) {
            slot = tab_insert(h);
            float* p = &d_latA[slot * LSTRIDE];
            atomicAdd(p + 0, s0);
            atomicAdd(p + 1, s1);
            atomicAdd(p + 2, s2);
            atomicAdd(p + 3, s3);
            atomicAdd(p + 4, s4);
        }
        slot = __shfl_sync(mask, slot, leader);
        d_slots[r * NPTS + n] = (unsigned)slot;
    }
}

// Resolve all 8 neighbor probes per occupied entry in one pass (MLP=8).
__global__ void k_nbr(int dh0, int dh1, int dh2, int dh3) {
    int total  = d_count;
    int stride = gridDim.x * blockDim.x;
    int dhs[4] = {dh0, dh1, dh2, dh3};
    for (int i = blockIdx.x * blockDim.x + threadIdx.x; i < total; i += stride) {
        int h = d_list[i].y;
#pragma unroll
        for (int k = 0; k < 4; k++) {
            d_nbr[(2 * k + 0) * LISTCAP + i] = tab_find(h + dhs[k]);
            d_nbr[(2 * k + 1) * LISTCAP + i] = tab_find(h - dhs[k]);
        }
    }
}

// Pure gather blur: no hashing, vector loads on padded rows.
__global__ void k_blur(int k, int srcIsA) {
    int total  = d_count;
    int stride = gridDim.x * blockDim.x;
    const float* src = srcIsA ? d_latA : d_latB;
    float*       dst = srcIsA ? d_latB : d_latA;

    for (int i = blockIdx.x * blockDim.x + threadIdx.x; i < total; i += stride) {
        int s = d_list[i].x;
        int p = d_nbr[(2 * k + 0) * LISTCAP + i];
        int q = d_nbr[(2 * k + 1) * LISTCAP + i];

        const float4* ps = (const float4*)&src[s * LSTRIDE];
        const float4* pp = (const float4*)&src[p * LSTRIDE];
        const float4* pq = (const float4*)&src[q * LSTRIDE];
        float4 cs = ps[0], cp = pp[0], cq = pq[0];
        float  es = src[s * LSTRIDE + 4], ep = src[p * LSTRIDE + 4], eq = src[q * LSTRIDE + 4];

        float4 o;
        o.x = cs.x + 0.5f * (cp.x + cq.x);
        o.y = cs.y + 0.5f * (cp.y + cq.y);
        o.z = cs.z + 0.5f * (cp.z + cq.z);
        o.w = cs.w + 0.5f * (cp.w + cq.w);
        ((float4*)&dst[s * LSTRIDE])[0] = o;
        dst[s * LSTRIDE + 4] = es + 0.5f * (ep + eq);
    }
}

__global__ void k_slice(float* __restrict__ out) {
    int n = blockIdx.x * blockDim.x + threadIdx.x;
    if (n >= NPTS) return;

    // Recompute nothing heavy: bary must match splat; recompute geometry.
    // (features depend only on coordinates; vg/sg constant across launch)
    // We stored slots, but bary must be recomputed — done via stored approach:
    // recompute from lattice() needs vg/sg; instead we re-derive from slots is
    // not possible, so bary recompute happens in k_slice2 below.
    (void)out; (void)n;
}

__global__ void k_slice2(const float* __restrict__ vg,
                         const float* __restrict__ sg,
                         float* __restrict__ out) {
    int n = blockIdx.x * blockDim.x + threadIdx.x;
    if (n >= NPTS) return;
    float f0, f1, f2;
    point_features(n, vg, sg, f0, f1, f2);

    int hh[4]; float bary[4];
    lattice(f0, f1, f2, hh, bary);

    float acc0 = 0.f, acc1 = 0.f, acc2 = 0.f, acc3 = 0.f, acc4 = 0.f;
#pragma unroll
    for (int r = 0; r < 4; r++) {
        unsigned s = d_slots[r * NPTS + n];
        float    w = bary[r];
        const float4 c = *(const float4*)&d_latA[s * LSTRIDE];
        float        e = d_latA[s * LSTRIDE + 4];
        acc0 += w * c.x;
        acc1 += w * c.y;
        acc2 += w * c.z;
        acc3 += w * c.w;
        acc4 += w * e;
    }
    const float alpha = 1.f / 1.125f;  // 1/(1 + 2^-PD)
    float norm = alpha * acc4 + 2.220446049250313e-16f;
    float inv  = 1.f / norm;
    out[0 * NPTS + n] = alpha * acc0 * inv;
    out[1 * NPTS + n] = alpha * acc1 * inv;
    out[2 * NPTS + n] = alpha * acc2 * inv;
    out[3 * NPTS + n] = alpha * acc3 * inv;
}

// Restore invariants: keys cleared, latA rows zeroed. latB occupied rows are
// overwritten before read next call; sentinel row stays zero.
__global__ void k_cleanup() {
    int total  = d_count;
    int stride = gridDim.x * blockDim.x;
    for (int i = blockIdx.x * blockDim.x + threadIdx.x; i < total; i += stride) {
        int s = d_list[i].x;
        d_keys[s] = EMPTYK;
        float4 z = make_float4(0.f, 0.f, 0.f, 0.f);
        ((float4*)&d_latA[s * LSTRIDE])[0] = z;
        d_latA[s * LSTRIDE + 4] = 0.f;
    }
}

extern "C" void kernel_launch(void* const* d_in, const int* in_sizes, int n_in,
                              void* d_out, int out_size) {
    const float* input = nullptr;
    const float* vg = nullptr;
    const float* sg = nullptr;
    for (int i = 0; i < n_in; i++) {
        if (in_sizes[i] == 4 * NPTS) input = (const float*)d_in[i];
        else if (in_sizes[i] == 3) {
            if (!vg) vg = (const float*)d_in[i];
            else     sg = (const float*)d_in[i];
        }
    }
    float* out = (float*)d_out;

    const int DH0 = -3 * (1 << 20) + (1 << 10) + 1;      // o = (-3, 1, 1)
    const int DH1 =      (1 << 20) - 3 * (1 << 10) + 1;  // o = (1, -3, 1)
    const int DH2 =      (1 << 20) + (1 << 10) - 3;      // o = (1, 1, -3)
    const int DH3 =      (1 << 20) + (1 << 10) + 1;      // o = (1, 1, 1)

    k_rstcnt<<<1, 1>>>();
    k_splat<<<NPTS / 256, 256>>>(input, vg, sg);
    k_nbr<<<1024, 128>>>(DH0, DH1, DH2, DH3);
    k_blur<<<1024, 128>>>(0, 1);  // A -> B
    k_blur<<<1024, 128>>>(1, 0);  // B -> A
    k_blur<<<1024, 128>>>(2, 1);  // A -> B
    k_blur<<<1024, 128>>>(3, 0);  // B -> A (final in A)
    k_slice2<<<NPTS / 256, 256>>>(vg, sg, out);
    k_cleanup<<<1024, 128>>>();
}

// round 4
// speedup vs baseline: 1.3960x; 1.0589x over previous
#include <cuda_runtime.h>

// Problem constants (fixed shapes for this problem instance)
#define Dz 64
#define Hy 128
#define Wx 128
#define NPTS (Dz * Hy * Wx)          // 1,048,576
#define TBITS 20
#define TSIZE (1 << TBITS)           // 1,048,576 slots
#define TMASK (TSIZE - 1)
#define LISTCAP (1 << 19)            // max distinct lattice vertices (actual ~1e3-1e5)
#define SENT LISTCAP                 // sentinel compact id: row stays all-zero
#define LSTRIDE 8                    // padded lattice row (floats)

// Scratch (device globals; zero-initialized at load). Key 0 == empty (packed
// hash is never 0). d_cid[slot] holds compact_id+1 (0 == unpublished).
__device__ int   d_keys[TSIZE];
__device__ int   d_cid[TSIZE];
__device__ int   d_hash[LISTCAP];
__device__ int   d_slotof[LISTCAP];
__device__ float d_latA[(LISTCAP + 1) * LSTRIDE];
__device__ float d_latB[(LISTCAP + 1) * LSTRIDE];
__device__ int   d_count;

__device__ __forceinline__ unsigned tab_start(int h) {
    return ((unsigned)h * 2654435761u) >> (32 - TBITS);
}

// Insert key, return compact id. Winners allocate an id and publish it;
// losers spin briefly until the winner publishes.
__device__ __forceinline__ int tab_insert(int h) {
    unsigned idx = tab_start(h);
    for (;;) {
        int prev = atomicCAS(&d_keys[idx], 0, h);
        if (prev == 0) {
            int id = atomicAdd(&d_count, 1);
            d_hash[id]   = h;
            d_slotof[id] = (int)idx;
            atomicExch(&d_cid[idx], id + 1);
            return id;
        }
        if (prev == h) {
            int c;
            while ((c = atomicAdd(&d_cid[idx], 0)) == 0) { }
            return c - 1;
        }
        idx = (idx + 1) & TMASK;
    }
}

// Lookup key -> compact id, or SENT if absent.
__device__ __forceinline__ int find_id(int h) {
    unsigned idx = tab_start(h);
    for (;;) {
        int k = d_keys[idx];
        if (k == h) return d_cid[idx] - 1;
        if (k == 0) return SENT;
        idx = (idx + 1) & TMASK;
    }
}

// Permutohedral lattice geometry: 4 packed keys + 4 barycentric weights.
__device__ __forceinline__ void lattice(float f0, float f1, float f2,
                                        int* hh, float* bary) {
    const float s0 = 2.3094010767585034f;
    const float s1 = 1.3333333333333333f;
    const float s2 = 0.9428090415820634f;
    float c0 = f0 * s0, c1 = f1 * s1, c2 = f2 * s2;
    float el[4];
    el[0] =  c0 + c1 + c2;
    el[1] = -c0 + c1 + c2;
    el[2] = -2.f * c1 + c2;
    el[3] = -3.f * c2;

    float rem0[4];
    float sum = 0.f;
#pragma unroll
    for (int i = 0; i < 4; i++) {
        float r = rintf(el[i] * 0.25f) * 4.f;   // nearest multiple of 4
        rem0[i] = r;
        sum += r;
    }

    float diff[4];
    int rank[4] = {0, 0, 0, 0};
#pragma unroll
    for (int i = 0; i < 4; i++) diff[i] = el[i] - rem0[i];
#pragma unroll
    for (int i = 0; i < 4; i++) {
#pragma unroll
        for (int j = i + 1; j < 4; j++) {
            if (diff[i] < diff[j]) rank[i]++; else rank[j]++;
        }
    }

    int off = (int)rintf(sum * 0.25f);
#pragma unroll
    for (int i = 0; i < 4; i++) {
        rank[i] += off;
        if (rank[i] < 0)      { rank[i] += 4; rem0[i] += 4.f; }
        else if (rank[i] > 3) { rank[i] -= 4; rem0[i] -= 4.f; }
    }

    float b[5] = {0.f, 0.f, 0.f, 0.f, 0.f};
#pragma unroll
    for (int i = 0; i < 4; i++) {
        float t = (el[i] - rem0[i]) * 0.25f;
        b[3 - rank[i]] += t;
        b[4 - rank[i]] -= t;
    }
    b[0] += 1.f + b[4];

    int r0 = (int)rem0[0], r1 = (int)rem0[1], r2 = (int)rem0[2];
#pragma unroll
    for (int r = 0; r < 4; r++) {
        int k0 = r0 + ((rank[0] >= 4 - r) ? r - 4 : r);
        int k1 = r1 + ((rank[1] >= 4 - r) ? r - 4 : r);
        int k2 = r2 + ((rank[2] >= 4 - r) ? r - 4 : r);
        hh[r]  = ((k0 + 512) << 20) + ((k1 + 512) << 10) + (k2 + 512);
        bary[r] = b[r];
    }
}

__device__ __forceinline__ void point_features(int n, const float* vg, const float* sg,
                                               float& f0, float& f1, float& f2) {
    int x = n & (Wx - 1);
    int y = (n >> 7) & (Hy - 1);
    int z = n >> 14;
    f0 = vg[0] * (float)z / sg[0];
    f1 = vg[2] * (float)y / sg[2];
    f2 = vg[1] * (float)x / sg[1];
}

__global__ void k_rstcnt() { d_count = 0; }

__global__ void k_splat(const float* __restrict__ vals,
                        const float* __restrict__ vg,
                        const float* __restrict__ sg) {
    int n = blockIdx.x * blockDim.x + threadIdx.x;
    float f0, f1, f2;
    point_features(n, vg, sg, f0, f1, f2);

    int hh[4]; float bary[4];
    lattice(f0, f1, f2, hh, bary);

    float v0 = vals[n];
    float v1 = vals[NPTS + n];
    float v2 = vals[2 * NPTS + n];
    float v3 = vals[3 * NPTS + n];

    int lane = threadIdx.x & 31;

#pragma unroll
    for (int r = 0; r < 4; r++) {
        int   h = hh[r];
        float w = bary[r];
        float a0 = w * v0, a1 = w * v1, a2 = w * v2, a3 = w * v3, a4 = w;

        // Segmented warp reduction: equal keys form (mostly) contiguous runs.
        int  hprev = __shfl_up_sync(0xffffffffu, h, 1);
        bool head  = (lane == 0) || (hprev != h);
        unsigned heads = __ballot_sync(0xffffffffu, head);
        unsigned above = (lane == 31) ? 0u : (heads & ~((2u << lane) - 1u));
        int end = above ? (__ffs(above) - 2) : 31;   // last lane of my segment

#pragma unroll
        for (int d = 1; d < 32; d <<= 1) {
            float t0 = __shfl_down_sync(0xffffffffu, a0, d);
            float t1 = __shfl_down_sync(0xffffffffu, a1, d);
            float t2 = __shfl_down_sync(0xffffffffu, a2, d);
            float t3 = __shfl_down_sync(0xffffffffu, a3, d);
            float t4 = __shfl_down_sync(0xffffffffu, a4, d);
            if (lane + d <= end) { a0 += t0; a1 += t1; a2 += t2; a3 += t3; a4 += t4; }
        }

        if (head) {
            int id = tab_insert(h);
            float* p = &d_latA[(size_t)id * LSTRIDE];
            atomicAdd(p + 0, a0);
            atomicAdd(p + 1, a1);
            atomicAdd(p + 2, a2);
            atomicAdd(p + 3, a3);
            atomicAdd(p + 4, a4);
        }
    }
}

// Blur one direction: compact rows, inline probes (table is cache-hot).
__global__ void k_blur(int dh, int srcIsA) {
    int total  = d_count;
    int stride = gridDim.x * blockDim.x;
    const float* src = srcIsA ? d_latA : d_latB;
    float*       dst = srcIsA ? d_latB : d_latA;

    for (int i = blockIdx.x * blockDim.x + threadIdx.x; i < total; i += stride) {
        int h = d_hash[i];
        int p = find_id(h + dh);
        int q = find_id(h - dh);

        float4 cs = *(const float4*)&src[(size_t)i * LSTRIDE];
        float4 cp = *(const float4*)&src[(size_t)p * LSTRIDE];
        float4 cq = *(const float4*)&src[(size_t)q * LSTRIDE];
        float  es = src[(size_t)i * LSTRIDE + 4];
        float  ep = src[(size_t)p * LSTRIDE + 4];
        float  eq = src[(size_t)q * LSTRIDE + 4];

        float4 o;
        o.x = cs.x + 0.5f * (cp.x + cq.x);
        o.y = cs.y + 0.5f * (cp.y + cq.y);
        o.z = cs.z + 0.5f * (cp.z + cq.z);
        o.w = cs.w + 0.5f * (cp.w + cq.w);
        *(float4*)&dst[(size_t)i * LSTRIDE] = o;
        dst[(size_t)i * LSTRIDE + 4] = es + 0.5f * (ep + eq);
    }
}

__global__ void k_slice(const float* __restrict__ vg,
                        const float* __restrict__ sg,
                        float* __restrict__ out) {
    int n = blockIdx.x * blockDim.x + threadIdx.x;
    float f0, f1, f2;
    point_features(n, vg, sg, f0, f1, f2);

    int hh[4]; float bary[4];
    lattice(f0, f1, f2, hh, bary);

    float acc0 = 0.f, acc1 = 0.f, acc2 = 0.f, acc3 = 0.f, acc4 = 0.f;
#pragma unroll
    for (int r = 0; r < 4; r++) {
        int id = find_id(hh[r]);   // key always present (inserted by splat)
        float w = bary[r];
        const float4 c = *(const float4*)&d_latA[(size_t)id * LSTRIDE];
        float        e = d_latA[(size_t)id * LSTRIDE + 4];
        acc0 += w * c.x;
        acc1 += w * c.y;
        acc2 += w * c.z;
        acc3 += w * c.w;
        acc4 += w * e;
    }
    const float alpha = 1.f / 1.125f;  // 1/(1 + 2^-PD)
    float norm = alpha * acc4 + 2.220446049250313e-16f;
    float inv  = 1.f / norm;
    out[0 * NPTS + n] = alpha * acc0 * inv;
    out[1 * NPTS + n] = alpha * acc1 * inv;
    out[2 * NPTS + n] = alpha * acc2 * inv;
    out[3 * NPTS + n] = alpha * acc3 * inv;
}

// Restore invariants for next call: clear table entries and compact latA rows.
// latB never needs clearing (occupied rows fully rewritten by blur pass 0;
// sentinel row never written).
__global__ void k_cleanup() {
    int total  = d_count;
    int stride = gridDim.x * blockDim.x;
    for (int i = blockIdx.x * blockDim.x + threadIdx.x; i < total; i += stride) {
        int s = d_slotof[i];
        d_keys[s] = 0;
        d_cid[s]  = 0;
        *(float4*)&d_latA[(size_t)i * LSTRIDE] = make_float4(0.f, 0.f, 0.f, 0.f);
        d_latA[(size_t)i * LSTRIDE + 4] = 0.f;
    }
}

extern "C" void kernel_launch(void* const* d_in, const int* in_sizes, int n_in,
                              void* d_out, int out_size) {
    const float* input = nullptr;
    const float* vg = nullptr;
    const float* sg = nullptr;
    for (int i = 0; i < n_in; i++) {
        if (in_sizes[i] == 4 * NPTS) input = (const float*)d_in[i];
        else if (in_sizes[i] == 3) {
            if (!vg) vg = (const float*)d_in[i];
            else     sg = (const float*)d_in[i];
        }
    }
    float* out = (float*)d_out;

    const int DH0 = -3 * (1 << 20) + (1 << 10) + 1;      // o = (-3, 1, 1)
    const int DH1 =      (1 << 20) - 3 * (1 << 10) + 1;  // o = (1, -3, 1)
    const int DH2 =      (1 << 20) + (1 << 10) - 3;      // o = (1, 1, -3)
    const int DH3 =      (1 << 20) + (1 << 10) + 1;      // o = (1, 1, 1)

    k_rstcnt<<<1, 1>>>();
    k_splat<<<NPTS / 256, 256>>>(input, vg, sg);
    k_blur<<<296, 128>>>(DH0, 1);  // A -> B
    k_blur<<<296, 128>>>(DH1, 0);  // B -> A
    k_blur<<<296, 128>>>(DH2, 1);  // A -> B
    k_blur<<<296, 128>>>(DH3, 0);  // B -> A (final in A)
    k_slice<<<NPTS / 256, 256>>>(vg, sg, out);
    k_cleanup<<<296, 128>>>();
}